// round 1
// baseline (speedup 1.0000x reference)
#include <cuda_runtime.h>
#include <math.h>

// Problem constants
#define B_  4
#define H_  384
#define W_  384
#define HW_ (H_*W_)
#define H2_ 192
#define W2_ 192

// ---------------- scratch (device globals; no allocation allowed) ------------
__device__ float g_in13[B_*13*HW_];        // concat input for unet conv_in
__device__ float g_out1[B_*64*HW_];        // unet out1; later reused as deform feat
__device__ float g_t1  [B_*64*H2_*W2_];
__device__ float g_t2  [B_*64*H2_*W2_];
__device__ float g_out2[B_*64*HW_];        // unet out2; later reused as h1
__device__ float g_mi  [B_*54*HW_];
__device__ float g_h2  [B_*64*HW_];

// ---------------- concat of the 5 input tensors into 13 channels -------------
__global__ void concat13_kernel(const float* __restrict__ a,  // x_rec (3)
                                const float* __restrict__ b,  // x_ref_near (3)
                                const float* __restrict__ c,  // x_ref_far (3)
                                const float* __restrict__ d,  // motion_near (2)
                                const float* __restrict__ e,  // motion_far (2)
                                float* __restrict__ out)
{
    int idx = blockIdx.x * blockDim.x + threadIdx.x;
    const int total = B_ * 13 * HW_;
    if (idx >= total) return;
    int pix = idx % HW_;
    int ch  = (idx / HW_) % 13;
    int bb  = idx / (HW_ * 13);
    float v;
    if      (ch < 3)  v = a[(bb*3 + ch    ) * HW_ + pix];
    else if (ch < 6)  v = b[(bb*3 + ch - 3) * HW_ + pix];
    else if (ch < 9)  v = c[(bb*3 + ch - 6) * HW_ + pix];
    else if (ch < 11) v = d[(bb*2 + ch - 9) * HW_ + pix];
    else              v = e[(bb*2 + ch -11) * HW_ + pix];
    out[idx] = v;
}

// ---------------- generic 3x3 conv (pad 1), NCHW fp32 ------------------------
// TW x TH output tile, each thread computes PXV vertically-strided pixels x 16 oc.
// ACT: 0 = none, 1 = relu, 2 = leaky(0.01), 3 = none + residual add
// Input may be a channel-concat of (inA: csplit ch) and (inB: CIN-csplit ch).
template<int TW, int TH, int PXV, int ICB, int STRIDE, int ACT>
__global__ void conv3x3_kernel(const float* __restrict__ inA,
                               const float* __restrict__ inB, int csplit,
                               const float* __restrict__ w,
                               const float* __restrict__ bias,
                               const float* __restrict__ resid,
                               float* __restrict__ out,
                               int CIN, int COUT, int Hin, int Win,
                               int Hout, int Wout)
{
    constexpr int OCB = 16;
    constexpr int IH  = (TH - 1) * STRIDE + 3;
    constexpr int IW  = (TW - 1) * STRIDE + 3;
    constexpr int NTH = TW * (TH / PXV);
    constexpr int RSTEP = TH / PXV;

    __shared__ float s_in[ICB][IH][IW];
    __shared__ float s_w[OCB][ICB][9];

    const int nOcB = (COUT + OCB - 1) / OCB;
    const int b    = blockIdx.z / nOcB;
    const int oc0  = (blockIdx.z % nOcB) * OCB;
    const int x0   = blockIdx.x * TW;
    const int y0   = blockIdx.y * TH;
    const int t    = threadIdx.x;
    const int tx   = t % TW;
    const int tyb  = t / TW;

    float acc[PXV][OCB];
#pragma unroll
    for (int p = 0; p < PXV; p++)
#pragma unroll
        for (int o = 0; o < OCB; o++) acc[p][o] = 0.f;

    const int in_y0 = y0 * STRIDE - 1;
    const int in_x0 = x0 * STRIDE - 1;

    for (int ic0 = 0; ic0 < CIN; ic0 += ICB) {
        const float* src;
        int cbase, ctot;
        if (ic0 < csplit) { src = inA; cbase = ic0;          ctot = csplit; }
        else              { src = inB; cbase = ic0 - csplit; ctot = CIN - csplit; }
        const int cmax = ctot - cbase;   // valid channels in this chunk (may exceed ICB)

        // stage input patch
        for (int idx = t; idx < ICB * IH * IW; idx += NTH) {
            int ic = idx / (IH * IW);
            int r  = (idx / IW) % IH;
            int c  = idx % IW;
            int gy = in_y0 + r, gx = in_x0 + c;
            float v = 0.f;
            if (ic < cmax && gy >= 0 && gy < Hin && gx >= 0 && gx < Win)
                v = src[((b * ctot + cbase + ic) * Hin + gy) * Win + gx];
            s_in[ic][r][c] = v;
        }
        // stage weights
        for (int idx = t; idx < OCB * ICB * 9; idx += NTH) {
            int o   = idx / (ICB * 9);
            int rem = idx % (ICB * 9);
            int ic  = rem / 9;
            int tap = rem % 9;
            float v = 0.f;
            if (oc0 + o < COUT && ic0 + ic < CIN)
                v = w[((oc0 + o) * CIN + ic0 + ic) * 9 + tap];
            s_w[o][ic][tap] = v;
        }
        __syncthreads();

#pragma unroll
        for (int ic = 0; ic < ICB; ic++) {
#pragma unroll
            for (int ky = 0; ky < 3; ky++) {
#pragma unroll
                for (int kx = 0; kx < 3; kx++) {
                    float vv[PXV];
#pragma unroll
                    for (int p = 0; p < PXV; p++)
                        vv[p] = s_in[ic][(tyb + p * RSTEP) * STRIDE + ky][tx * STRIDE + kx];
#pragma unroll
                    for (int o = 0; o < OCB; o++) {
                        float wv = s_w[o][ic][ky * 3 + kx];
#pragma unroll
                        for (int p = 0; p < PXV; p++)
                            acc[p][o] += vv[p] * wv;
                    }
                }
            }
        }
        __syncthreads();
    }

#pragma unroll
    for (int p = 0; p < PXV; p++) {
        int gy = y0 + tyb + p * RSTEP;
        int gx = x0 + tx;
        if (gy >= Hout || gx >= Wout) continue;
#pragma unroll
        for (int o = 0; o < OCB; o++) {
            if (oc0 + o >= COUT) break;
            float r = acc[p][o] + bias[oc0 + o];
            if (ACT == 1) r = fmaxf(r, 0.f);
            if (ACT == 2) r = (r > 0.f) ? r : 0.01f * r;
            int oidx = ((b * COUT + oc0 + o) * Hout + gy) * Wout + gx;
            if (ACT == 3) r += resid[oidx];
            out[oidx] = r;
        }
    }
}

// ---------------- 4x4 stride-2 conv-transpose (pad=... exactly per ref) ------
// out[o,Y,X] = relu( b[o] + sum_i sum_{j,l in 0..1} t[i, iy, ix] * w[i,o,3-ky,3-kx] )
//   ky = (Y&1) + 2j, kx = (X&1) + 2l, iy = ((Y+ (Y&1))>>1) + j - 1  (similarly ix)
// CIN = COUT = 64. Tile 16x8, OCB=16, ICB=16, 128 threads.
__global__ void convT4x4_kernel(const float* __restrict__ in,
                                const float* __restrict__ w,
                                const float* __restrict__ bias,
                                float* __restrict__ out,
                                int Hin, int Win, int Hout, int Wout)
{
    __shared__ float s_in[16][6][10];
    __shared__ float s_w[16][16][16];   // [oc][ic][r*4+c]

    const int b   = blockIdx.z / 4;
    const int oc0 = (blockIdx.z % 4) * 16;
    const int x0  = blockIdx.x * 16;
    const int y0  = blockIdx.y * 8;
    const int t   = threadIdx.x;
    const int tx  = t % 16;
    const int ty  = t / 16;
    const int Y = y0 + ty, X = x0 + tx;
    const int pY = ty & 1, pX = tx & 1;
    const int rowb = (ty + pY) >> 1;   // + j gives patch row
    const int colb = (tx + pX) >> 1;   // + l gives patch col
    const int iy0 = (y0 >> 1) - 1;
    const int ix0 = (x0 >> 1) - 1;

    float acc[16];
#pragma unroll
    for (int o = 0; o < 16; o++) acc[o] = 0.f;

    for (int ic0 = 0; ic0 < 64; ic0 += 16) {
        for (int idx = t; idx < 16 * 6 * 10; idx += 128) {
            int ic = idx / 60;
            int r  = (idx / 10) % 6;
            int c  = idx % 10;
            int gy = iy0 + r, gx = ix0 + c;
            float v = 0.f;
            if (gy >= 0 && gy < Hin && gx >= 0 && gx < Win)
                v = in[((b * 64 + ic0 + ic) * Hin + gy) * Win + gx];
            s_in[ic][r][c] = v;
        }
        for (int idx = t; idx < 16 * 16 * 16; idx += 128) {
            int o  = idx / 256;
            int ic = (idx / 16) % 16;
            int tap = idx % 16;
            // w layout (I=64, O=64, 4, 4); need w[ic][oc][tap]
            s_w[o][ic][tap] = w[((ic0 + ic) * 64 + oc0 + o) * 16 + tap];
        }
        __syncthreads();

#pragma unroll
        for (int ic = 0; ic < 16; ic++) {
#pragma unroll
            for (int j = 0; j < 2; j++) {
#pragma unroll
                for (int l = 0; l < 2; l++) {
                    float v = s_in[ic][rowb + j][colb + l];
                    int tap = (3 - pY - 2*j) * 4 + (3 - pX - 2*l);
#pragma unroll
                    for (int o = 0; o < 16; o++)
                        acc[o] += v * s_w[o][ic][tap];
                }
            }
        }
        __syncthreads();
    }

#pragma unroll
    for (int o = 0; o < 16; o++) {
        float r = acc[o] + bias[oc0 + o];
        r = fmaxf(r, 0.f);
        out[((b * 64 + oc0 + o) * Hout + Y) * Wout + X] = r;
    }
}

// ---------------- fused deformable conv ---------------------------------------
// Reads mi (54ch) + motion directly, computes offsets/masks inline, bilinear
// gathers from x_ref_near/far (3 ch each, dg=2, K=9), contracts with dw -> 64 ch.
__global__ void deform_kernel(const float* __restrict__ mi,
                              const float* __restrict__ mo_near,
                              const float* __restrict__ mo_far,
                              const float* __restrict__ ref_near,
                              const float* __restrict__ ref_far,
                              const float* __restrict__ dw,
                              const float* __restrict__ db,
                              float* __restrict__ out)
{
    __shared__ float s_w[64 * 54];
    __shared__ float s_b[64];
    const int t = threadIdx.x;
    for (int i = t; i < 64 * 54; i += 128) s_w[i] = dw[i];  // same flat layout
    if (t < 64) s_b[t] = db[t];
    __syncthreads();

    int id = blockIdx.x * 128 + t;
    if (id >= B_ * HW_) return;
    const int b   = id / HW_;
    const int rem = id % HW_;
    const int y = rem / W_;
    const int x = rem % W_;

    float vbuf[54];
#pragma unroll
    for (int g = 0; g < 2; g++) {
        const float* mo = g ? mo_far : mo_near;
        const float* rf = g ? ref_far : ref_near;
        const float m0 = mo[((b * 2 + 0) * H_ + y) * W_ + x];
        const float m1 = mo[((b * 2 + 1) * H_ + y) * W_ + x];
        const int mibase = b * 54 + g * 27;
#pragma unroll
        for (int k = 0; k < 9; k++) {
            float ody = mi[((mibase + 2*k    ) * H_ + y) * W_ + x];
            float odx = mi[((mibase + 2*k + 1) * H_ + y) * W_ + x];
            float msv = mi[((mibase + 18 + k ) * H_ + y) * W_ + x];
            float msk = 1.f / (1.f + expf(-msv));
            float dy = 10.f * tanhf(ody) + m1;   // motion[:, ::-1]: even ch -> m1
            float dx = 10.f * tanhf(odx) + m0;
            float py = (float)y + (float)(k / 3 - 1) + dy;
            float px = (float)x + (float)(k % 3 - 1) + dx;
            float fy = floorf(py), fx = floorf(px);
            int y0i = (int)fy, x0i = (int)fx;
            float wy = py - fy, wx = px - fx;
            bool vy0 = (y0i >= 0)     && (y0i < H_);
            bool vy1 = (y0i + 1 >= 0) && (y0i + 1 < H_);
            bool vx0 = (x0i >= 0)     && (x0i < W_);
            bool vx1 = (x0i + 1 >= 0) && (x0i + 1 < W_);
            int cy0 = min(max(y0i,     0), H_ - 1);
            int cy1 = min(max(y0i + 1, 0), H_ - 1);
            int cx0 = min(max(x0i,     0), W_ - 1);
            int cx1 = min(max(x0i + 1, 0), W_ - 1);
            float w00 = (1.f - wy) * (1.f - wx) * ((vy0 && vx0) ? 1.f : 0.f);
            float w01 = (1.f - wy) * wx         * ((vy0 && vx1) ? 1.f : 0.f);
            float w10 = wy * (1.f - wx)         * ((vy1 && vx0) ? 1.f : 0.f);
            float w11 = wy * wx                 * ((vy1 && vx1) ? 1.f : 0.f);
#pragma unroll
            for (int c = 0; c < 3; c++) {
                const float* base = rf + (b * 3 + c) * HW_;
                float v = w00 * base[cy0 * W_ + cx0]
                        + w01 * base[cy0 * W_ + cx1]
                        + w10 * base[cy1 * W_ + cx0]
                        + w11 * base[cy1 * W_ + cx1];
                vbuf[(g * 3 + c) * 9 + k] = v * msk;
            }
        }
    }

#pragma unroll 4
    for (int o = 0; o < 64; o++) {
        float acc = s_b[o];
#pragma unroll
        for (int j = 0; j < 54; j++)
            acc += vbuf[j] * s_w[o * 54 + j];
        out[((b * 64 + o) * H_ + y) * W_ + x] = acc;
    }
}

// ---------------------------------------------------------------------------
extern "C" void kernel_launch(void* const* d_in, const int* in_sizes, int n_in,
                              void* d_out, int out_size)
{
    const float* x_rec = (const float*)d_in[0];
    const float* x_rn  = (const float*)d_in[1];
    const float* x_rf  = (const float*)d_in[2];
    const float* mo_n  = (const float*)d_in[3];
    const float* mo_f  = (const float*)d_in[4];
    const float* uw_in = (const float*)d_in[5];
    const float* ub_in = (const float*)d_in[6];
    const float* uw_t1 = (const float*)d_in[7];
    const float* ub_t1 = (const float*)d_in[8];
    const float* uw_t2 = (const float*)d_in[9];
    const float* ub_t2 = (const float*)d_in[10];
    const float* uw_tt = (const float*)d_in[11];
    const float* ub_tt = (const float*)d_in[12];
    const float* uw_o  = (const float*)d_in[13];
    const float* ub_o  = (const float*)d_in[14];
    const float* dw    = (const float*)d_in[15];
    const float* db    = (const float*)d_in[16];
    const float* qw1   = (const float*)d_in[17];
    const float* qb1   = (const float*)d_in[18];
    const float* qw2   = (const float*)d_in[19];
    const float* qb2   = (const float*)d_in[20];
    const float* qw3   = (const float*)d_in[21];
    const float* qb3   = (const float*)d_in[22];
    float* outp = (float*)d_out;

    float *in13, *out1, *t1, *t2, *out2, *mi, *h2;
    cudaGetSymbolAddress((void**)&in13, g_in13);
    cudaGetSymbolAddress((void**)&out1, g_out1);
    cudaGetSymbolAddress((void**)&t1,   g_t1);
    cudaGetSymbolAddress((void**)&t2,   g_t2);
    cudaGetSymbolAddress((void**)&out2, g_out2);
    cudaGetSymbolAddress((void**)&mi,   g_mi);
    cudaGetSymbolAddress((void**)&h2,   g_h2);
    float* feat = out1;   // reuse (out1 dead after mi conv)
    float* h1   = out2;   // reuse (out2 dead after mi conv)

    // 1) concat 13-channel unet input
    {
        int total = B_ * 13 * HW_;
        concat13_kernel<<<(total + 255) / 256, 256>>>(x_rec, x_rn, x_rf, mo_n, mo_f, in13);
    }
    // 2) out1 = relu(conv 13->64) @384
    conv3x3_kernel<16,16,2,8,1,1><<<dim3(W_/16, H_/16, B_*4), 128>>>(
        in13, nullptr, 13, uw_in, ub_in, nullptr, out1, 13, 64, H_, W_, H_, W_);
    // 3) t1 = relu(conv 64->64 stride2) @192
    conv3x3_kernel<16,8,2,8,2,1><<<dim3(W2_/16, H2_/8, B_*4), 64>>>(
        out1, nullptr, 64, uw_t1, ub_t1, nullptr, t1, 64, 64, H_, W_, H2_, W2_);
    // 4) t2 = relu(conv 64->64) @192
    conv3x3_kernel<16,16,2,8,1,1><<<dim3(W2_/16, H2_/16, B_*4), 128>>>(
        t1, nullptr, 64, uw_t2, ub_t2, nullptr, t2, 64, 64, H2_, W2_, H2_, W2_);
    // 5) out2 = relu(convT 4x4 s2) @384
    convT4x4_kernel<<<dim3(W_/16, H_/8, B_*4), 128>>>(
        t2, uw_tt, ub_tt, out2, H2_, W2_, H_, W_);
    // 6) mi = conv(concat[out1,out2] 128 -> 54) @384  (no activation)
    conv3x3_kernel<16,16,2,8,1,0><<<dim3(W_/16, H_/16, B_*4), 128>>>(
        out1, out2, 64, uw_o, ub_o, nullptr, mi, 128, 54, H_, W_, H_, W_);
    // 7) feat = deformable conv (fused offset/mask math)
    deform_kernel<<<(B_ * HW_ + 127) / 128, 128>>>(
        mi, mo_n, mo_f, x_rn, x_rf, dw, db, feat);
    // 8) h1 = leaky(conv 64->64)
    conv3x3_kernel<16,16,2,8,1,2><<<dim3(W_/16, H_/16, B_*4), 128>>>(
        feat, nullptr, 64, qw1, qb1, nullptr, h1, 64, 64, H_, W_, H_, W_);
    // 9) h2 = leaky(conv 64->64)
    conv3x3_kernel<16,16,2,8,1,2><<<dim3(W_/16, H_/16, B_*4), 128>>>(
        h1, nullptr, 64, qw2, qb2, nullptr, h2, 64, 64, H_, W_, H_, W_);
    // 10) out = x_rec + conv(h2, 64->3)
    conv3x3_kernel<16,16,2,8,1,3><<<dim3(W_/16, H_/16, B_*1), 128>>>(
        h2, nullptr, 64, qw3, qb3, x_rec, outp, 64, 3, H_, W_, H_, W_);
}